// round 1
// baseline (speedup 1.0000x reference)
#include <cuda_runtime.h>
#include <cstdint>

#define BB   2
#define CC   64
#define HH   256
#define WW   256
#define KK   9          // 3x3 taps
#define ND   3          // dilations {1,2,4}
#define NOFF 54         // 2*KK*ND offset channels
#define PX   64         // pixels per main-kernel block (along W)
#define SSTR 68         // padded row stride for sS tile

// ---------------- scratch (device globals: no allocation allowed) ----------
__device__ float g_xT[(size_t)BB * HH * WW * CC];     // NHWC transpose of x
__device__ float g_off[(size_t)BB * HH * WW * NOFF];  // offsets, (b,h,w,54)
__device__ float g_weff[(size_t)ND * KK * CC * CC];   // fused weights [tap][c][oo]

// ---------------- 1) x (B,C,H,W) -> g_xT (B,H,W,C) --------------------------
__global__ void transpose_kernel(const float* __restrict__ x) {
    __shared__ float tile[32][33];
    int bh = blockIdx.z;               // b*HH + h
    int b  = bh / HH, h = bh % HH;
    int w0 = blockIdx.x * 32;
    int c0 = blockIdx.y * 32;
    int tx = threadIdx.x, ty = threadIdx.y;   // (32, 8)

    #pragma unroll
    for (int j = 0; j < 4; j++) {
        int c = c0 + ty + j * 8;
        tile[ty + j * 8][tx] = x[(((size_t)b * CC + c) * HH + h) * WW + (w0 + tx)];
    }
    __syncthreads();
    #pragma unroll
    for (int j = 0; j < 4; j++) {
        int w = w0 + ty + j * 8;
        g_xT[(((size_t)b * HH + h) * WW + w) * CC + (c0 + tx)] = tile[tx][ty + j * 8];
    }
}

// ---------------- 2) Weff[i][k][c][oo] = sum_o Wfuse[oo, i*64+o] * Wd[i,o,c,k]
__global__ void weff_kernel(const float* __restrict__ Wd,
                            const float* __restrict__ Wfuse) {
    int idx = blockIdx.x * 256 + threadIdx.x;
    if (idx >= ND * KK * CC * CC) return;
    int oo = idx % CC;
    int c  = (idx / CC) % CC;
    int k  = (idx / (CC * CC)) % KK;
    int i  = idx / (CC * CC * KK);
    float acc = 0.f;
    #pragma unroll 8
    for (int o = 0; o < CC; o++) {
        acc = fmaf(Wfuse[oo * (ND * CC) + i * CC + o],
                   Wd[(((size_t)(i * CC + o) * CC + c) * KK) + k], acc);
    }
    g_weff[idx] = acc;
}

// ---------------- 3) offset conv: off[b,h,w,oc] = boff[oc] + 3x3 conv -------
__global__ __launch_bounds__(256)
void offconv_kernel(const float* __restrict__ x,
                    const float* __restrict__ Woff,
                    const float* __restrict__ boff) {
    __shared__ float ws[NOFF * KK];   // weight slice for current input channel
    int bh = blockIdx.x;              // b*HH + h
    int b  = bh / HH, h = bh % HH;
    int w  = threadIdx.x;             // one pixel per thread, full row

    float acc[NOFF];
    #pragma unroll
    for (int oc = 0; oc < NOFF; oc++) acc[oc] = 0.f;

    const float* xb = x + (size_t)b * CC * HH * WW;

    for (int c = 0; c < CC; c++) {
        __syncthreads();
        for (int t = threadIdx.x; t < NOFF * KK; t += 256)
            ws[t] = Woff[(size_t)(t / KK) * CC * KK + (size_t)c * KK + (t % KK)];
        __syncthreads();

        float xv[9];
        #pragma unroll
        for (int ky = 0; ky < 3; ky++) {
            #pragma unroll
            for (int kx = 0; kx < 3; kx++) {
                int yy = h + ky - 1, xx = w + kx - 1;
                float v = 0.f;
                if (yy >= 0 && yy < HH && xx >= 0 && xx < WW)
                    v = xb[((size_t)c * HH + yy) * WW + xx];
                xv[ky * 3 + kx] = v;
            }
        }
        #pragma unroll
        for (int oc = 0; oc < NOFF; oc++) {
            float a = acc[oc];
            #pragma unroll
            for (int k = 0; k < 9; k++) a = fmaf(xv[k], ws[oc * KK + k], a);
            acc[oc] = a;
        }
    }

    size_t base = ((size_t)(b * HH + h) * WW + w) * NOFF;
    #pragma unroll
    for (int oc = 0; oc < NOFF; oc++)
        g_off[base + oc] = acc[oc] + __ldg(&boff[oc]);
}

// ---------------- 4) main: bilinear gather + fused einsum -------------------
// out[b,oo,h,w] = sum_{tap=(i,k)} sum_c Weff[tap][c][oo] * bilin(x, c, tap, px)
__global__ __launch_bounds__(256)
void main_kernel(float* __restrict__ out) {
    __shared__ float sS[PX * SSTR];       // sampled values (px, c), padded
    __shared__ float sW[CC * CC];         // Weff tile for current tap (c, oo)
    __shared__ float sOff[PX * NOFF];     // per-pixel offsets

    int bh = blockIdx.y;                  // b*HH + h
    int b  = bh / HH, h = bh % HH;
    int w0 = blockIdx.x * PX;
    int tid = threadIdx.x;

    // load per-pixel offsets (coalesced)
    for (int t = tid; t < PX * NOFF; t += 256) {
        int px = t / NOFF, ch = t % NOFF;
        sOff[px * NOFF + ch] =
            g_off[((size_t)(b * HH + h) * WW + (w0 + px)) * NOFF + ch];
    }

    float acc[4][4];
    #pragma unroll
    for (int p = 0; p < 4; p++)
        #pragma unroll
        for (int q = 0; q < 4; q++) acc[p][q] = 0.f;

    int pxg  = tid / 16;          // 16 pixel-groups of 4
    int ocg  = tid % 16;          // 16 oc-groups of 4
    int s_px = tid >> 2;          // sampler: pixel 0..63
    int s_cq = (tid & 3) * 16;    // sampler: channel chunk base

    const float* xTb = g_xT + (size_t)b * HH * WW * CC;

    for (int tap = 0; tap < ND * KK; tap++) {
        int i = tap / KK, k = tap % KK;
        int d = (i == 0) ? 1 : ((i == 1) ? 2 : 4);

        __syncthreads();   // previous tap consumers done with sS / sW

        // stage Weff[tap] (64x64) into smem
        {
            const float4* src = (const float4*)(g_weff + (size_t)tap * CC * CC);
            float4* dst = (float4*)sW;
            #pragma unroll
            for (int t = tid; t < CC * CC / 4; t += 256) dst[t] = src[t];
        }

        // sample 16 channels for this thread's pixel
        {
            float dy = sOff[s_px * NOFF + i * 2 * KK + 2 * k];
            float dx = sOff[s_px * NOFF + i * 2 * KK + 2 * k + 1];
            float ys = (float)h + (float)((k / 3 - 1) * d) + dy;
            float xs = (float)(w0 + s_px) + (float)((k % 3 - 1) * d) + dx;

            float y0f = floorf(ys), x0f = floorf(xs);
            float wy1 = ys - y0f, wx1 = xs - x0f;
            float wy0 = 1.f - wy1, wx0 = 1.f - wx1;
            float y1f = y0f + 1.f, x1f = x0f + 1.f;

            float vy0 = (y0f >= 0.f && y0f <= (float)(HH - 1)) ? 1.f : 0.f;
            float vy1 = (y1f >= 0.f && y1f <= (float)(HH - 1)) ? 1.f : 0.f;
            float vx0 = (x0f >= 0.f && x0f <= (float)(WW - 1)) ? 1.f : 0.f;
            float vx1 = (x1f >= 0.f && x1f <= (float)(WW - 1)) ? 1.f : 0.f;

            int iy0 = (int)fminf(fmaxf(y0f, 0.f), (float)(HH - 1));
            int iy1 = (int)fminf(fmaxf(y1f, 0.f), (float)(HH - 1));
            int ix0 = (int)fminf(fmaxf(x0f, 0.f), (float)(WW - 1));
            int ix1 = (int)fminf(fmaxf(x1f, 0.f), (float)(WW - 1));

            float cw[4];
            cw[0] = wy0 * wx0 * vy0 * vx0;
            cw[1] = wy0 * wx1 * vy0 * vx1;
            cw[2] = wy1 * wx0 * vy1 * vx0;
            cw[3] = wy1 * wx1 * vy1 * vx1;

            const float* ptr[4];
            ptr[0] = xTb + ((size_t)iy0 * WW + ix0) * CC + s_cq;
            ptr[1] = xTb + ((size_t)iy0 * WW + ix1) * CC + s_cq;
            ptr[2] = xTb + ((size_t)iy1 * WW + ix0) * CC + s_cq;
            ptr[3] = xTb + ((size_t)iy1 * WW + ix1) * CC + s_cq;

            float r[16];
            #pragma unroll
            for (int j = 0; j < 16; j++) r[j] = 0.f;

            #pragma unroll
            for (int cor = 0; cor < 4; cor++) {
                float cwt = cw[cor];
                const float4* src = (const float4*)ptr[cor];
                #pragma unroll
                for (int j4 = 0; j4 < 4; j4++) {
                    float4 v = __ldg(&src[j4]);
                    r[j4 * 4 + 0] = fmaf(cwt, v.x, r[j4 * 4 + 0]);
                    r[j4 * 4 + 1] = fmaf(cwt, v.y, r[j4 * 4 + 1]);
                    r[j4 * 4 + 2] = fmaf(cwt, v.z, r[j4 * 4 + 2]);
                    r[j4 * 4 + 3] = fmaf(cwt, v.w, r[j4 * 4 + 3]);
                }
            }
            #pragma unroll
            for (int j4 = 0; j4 < 4; j4++) {
                *(float4*)&sS[s_px * SSTR + s_cq + j4 * 4] =
                    make_float4(r[j4 * 4 + 0], r[j4 * 4 + 1],
                                r[j4 * 4 + 2], r[j4 * 4 + 3]);
            }
        }

        __syncthreads();

        // accumulate: acc[p][q] += sS[px,c] * sW[c,oo]
        #pragma unroll 4
        for (int c = 0; c < CC; c++) {
            float4 wv = *(const float4*)&sW[c * CC + ocg * 4];
            float s0 = sS[(pxg * 4 + 0) * SSTR + c];
            float s1 = sS[(pxg * 4 + 1) * SSTR + c];
            float s2 = sS[(pxg * 4 + 2) * SSTR + c];
            float s3 = sS[(pxg * 4 + 3) * SSTR + c];
            acc[0][0] = fmaf(s0, wv.x, acc[0][0]);
            acc[0][1] = fmaf(s0, wv.y, acc[0][1]);
            acc[0][2] = fmaf(s0, wv.z, acc[0][2]);
            acc[0][3] = fmaf(s0, wv.w, acc[0][3]);
            acc[1][0] = fmaf(s1, wv.x, acc[1][0]);
            acc[1][1] = fmaf(s1, wv.y, acc[1][1]);
            acc[1][2] = fmaf(s1, wv.z, acc[1][2]);
            acc[1][3] = fmaf(s1, wv.w, acc[1][3]);
            acc[2][0] = fmaf(s2, wv.x, acc[2][0]);
            acc[2][1] = fmaf(s2, wv.y, acc[2][1]);
            acc[2][2] = fmaf(s2, wv.z, acc[2][2]);
            acc[2][3] = fmaf(s2, wv.w, acc[2][3]);
            acc[3][0] = fmaf(s3, wv.x, acc[3][0]);
            acc[3][1] = fmaf(s3, wv.y, acc[3][1]);
            acc[3][2] = fmaf(s3, wv.z, acc[3][2]);
            acc[3][3] = fmaf(s3, wv.w, acc[3][3]);
        }
    }

    // epilogue: out (B, 64, H, W)
    #pragma unroll
    for (int q = 0; q < 4; q++) {
        #pragma unroll
        for (int p = 0; p < 4; p++) {
            out[((size_t)(b * CC + ocg * 4 + q) * HH + h) * WW + w0 + pxg * 4 + p]
                = acc[p][q];
        }
    }
}

// ---------------- launch ----------------------------------------------------
extern "C" void kernel_launch(void* const* d_in, const int* in_sizes, int n_in,
                              void* d_out, int out_size) {
    const float* x     = (const float*)d_in[0];
    const float* Woff  = (const float*)d_in[1];
    const float* boff  = (const float*)d_in[2];
    const float* Wd    = (const float*)d_in[3];
    const float* Wfuse = (const float*)d_in[4];
    float* out = (float*)d_out;

    transpose_kernel<<<dim3(WW / 32, CC / 32, BB * HH), dim3(32, 8)>>>(x);
    weff_kernel<<<(ND * KK * CC * CC + 255) / 256, 256>>>(Wd, Wfuse);
    offconv_kernel<<<BB * HH, 256>>>(x, Woff, boff);
    main_kernel<<<dim3(WW / PX, BB * HH), 256>>>(out);
}

// round 2
// speedup vs baseline: 1.1959x; 1.1959x over previous
#include <cuda_runtime.h>
#include <cstdint>

#define BB   2
#define CC   64
#define HH   256
#define WW   256
#define KK   9
#define ND   3
#define NOFF 54
#define PX   64
#define SSTR 68          // floats per sS row (64 + 4 pad)

typedef unsigned long long ull;

#define FMA2(d, a, b, c) asm("fma.rn.f32x2 %0, %1, %2, %3;" : "=l"(d) : "l"(a), "l"(b), "l"(c))
#define PACK2(d, lo, hi) asm("mov.b64 %0, {%1, %2};" : "=l"(d) : "f"(lo), "f"(hi))
#define UNPACK2(lo, hi, s) asm("mov.b64 {%0, %1}, %2;" : "=f"(lo), "=f"(hi) : "l"(s))

// ---------------- scratch ----------------------------------------------------
__device__ float g_xT[(size_t)BB * HH * WW * CC];     // NHWC transpose of x
__device__ float g_off[(size_t)BB * HH * WW * NOFF];  // offsets (b,h,w,54)
__device__ float g_weff[(size_t)ND * KK * CC * CC];   // fused weights [tap][c][oo]

// ---------------- 1) transpose x -> NHWC -------------------------------------
__global__ void transpose_kernel(const float* __restrict__ x) {
    __shared__ float tile[32][33];
    int bh = blockIdx.z;
    int b  = bh / HH, h = bh % HH;
    int w0 = blockIdx.x * 32;
    int c0 = blockIdx.y * 32;
    int tx = threadIdx.x, ty = threadIdx.y;

    #pragma unroll
    for (int j = 0; j < 4; j++) {
        int c = c0 + ty + j * 8;
        tile[ty + j * 8][tx] = x[(((size_t)b * CC + c) * HH + h) * WW + (w0 + tx)];
    }
    __syncthreads();
    #pragma unroll
    for (int j = 0; j < 4; j++) {
        int w = w0 + ty + j * 8;
        g_xT[(((size_t)b * HH + h) * WW + w) * CC + (c0 + tx)] = tile[tx][ty + j * 8];
    }
}

// ---------------- 2) Weff ----------------------------------------------------
__global__ void weff_kernel(const float* __restrict__ Wd,
                            const float* __restrict__ Wfuse) {
    int idx = blockIdx.x * 256 + threadIdx.x;
    if (idx >= ND * KK * CC * CC) return;
    int oo = idx % CC;
    int c  = (idx / CC) % CC;
    int k  = (idx / (CC * CC)) % KK;
    int i  = idx / (CC * CC * KK);
    float acc = 0.f;
    #pragma unroll 8
    for (int o = 0; o < CC; o++) {
        acc = fmaf(Wfuse[oo * (ND * CC) + i * CC + o],
                   Wd[(((size_t)(i * CC + o) * CC + c) * KK) + k], acc);
    }
    g_weff[idx] = acc;
}

// ---------------- 3) offset conv (register-tiled, FFMA2) ---------------------
// block = 1 image row (256 px), 256 threads = 32 px-groups(8px) x 8 oc-groups(7oc)
__global__ __launch_bounds__(256)
void offconv_kernel(const float* __restrict__ x,
                    const float* __restrict__ Woff,
                    const float* __restrict__ boff) {
    __shared__ float xs[2][3][264];     // 3 rows, 258 used (+pad), x[xx+1]
    __shared__ float2 w2[2][56 * 9];    // duplicated weight pairs

    int bh = blockIdx.x;
    int b  = bh / HH, h = bh % HH;
    int tid = threadIdx.x;
    int ocg = tid & 7;                  // oc group: oc = ocg*7 + j (j<7)
    int pxg = tid >> 3;                 // px group: px0 = pxg*8
    int px0 = pxg * 8;

    const float* xb = x + (size_t)b * CC * HH * WW;

    ull acc2[7][4];
    #pragma unroll
    for (int j = 0; j < 7; j++)
        #pragma unroll
        for (int pr = 0; pr < 4; pr++) acc2[j][pr] = 0ull;

    // stage c = 0 into buffer 0
    {
        #pragma unroll
        for (int r = 0; r < 3; r++) {
            int yy = h - 1 + r;
            int xx = tid - 1;
            float v = 0.f;
            if (yy >= 0 && yy < HH && xx >= 0)   // xx < 255 guaranteed (tid<256 -> xx<=254)
                v = xb[((size_t)0 * HH + yy) * WW + xx];
            xs[0][r][tid] = v;
            if (tid < 2) {
                int xx2 = tid + 255;
                float v2 = 0.f;
                if (yy >= 0 && yy < HH && xx2 < WW)
                    v2 = xb[((size_t)0 * HH + yy) * WW + xx2];
                xs[0][r][tid + 256] = v2;
            }
        }
        for (int t = tid; t < 56 * 9; t += 256) {
            int oc = t / 9, k = t % 9;
            float wv = (oc < NOFF) ? Woff[(size_t)oc * CC * KK + 0 * KK + k] : 0.f;
            w2[0][t] = make_float2(wv, wv);
        }
    }
    __syncthreads();

    int p = 0;
    for (int c = 0; c < CC; c++) {
        // -- issue stage loads for c+1 into registers --
        float rx[3], rx2[3], rw0 = 0.f, rw1 = 0.f;
        int cn = c + 1;
        if (cn < CC) {
            #pragma unroll
            for (int r = 0; r < 3; r++) {
                int yy = h - 1 + r;
                int xx = tid - 1;
                rx[r] = 0.f; rx2[r] = 0.f;
                if (yy >= 0 && yy < HH && xx >= 0)
                    rx[r] = xb[((size_t)cn * HH + yy) * WW + xx];
                if (tid < 2) {
                    int xx2 = tid + 255;
                    if (yy >= 0 && yy < HH && xx2 < WW)
                        rx2[r] = xb[((size_t)cn * HH + yy) * WW + xx2];
                }
            }
            {
                int t = tid;
                int oc = t / 9, k = t % 9;
                rw0 = (oc < NOFF) ? Woff[(size_t)oc * CC * KK + (size_t)cn * KK + k] : 0.f;
                if (tid < 56 * 9 - 256) {
                    int t2 = tid + 256;
                    int oc2 = t2 / 9, k2 = t2 % 9;
                    rw1 = (oc2 < NOFF) ? Woff[(size_t)oc2 * CC * KK + (size_t)cn * KK + k2] : 0.f;
                }
            }
        }

        // -- compute channel c from buffer p --
        #pragma unroll
        for (int ky = 0; ky < 3; ky++) {
            float xv[10];
            #pragma unroll
            for (int jj = 0; jj < 10; jj++) xv[jj] = xs[p][ky][px0 + jj];
            ull xp[9];
            #pragma unroll
            for (int m = 0; m < 9; m++) PACK2(xp[m], xv[m], xv[m + 1]);

            #pragma unroll
            for (int j = 0; j < 7; j++) {
                #pragma unroll
                for (int kx = 0; kx < 3; kx++) {
                    ull wd = *(const ull*)&w2[p][(ocg * 7 + j) * 9 + ky * 3 + kx];
                    #pragma unroll
                    for (int pr = 0; pr < 4; pr++)
                        FMA2(acc2[j][pr], xp[2 * pr + kx], wd, acc2[j][pr]);
                }
            }
        }

        // -- store staged regs into other buffer --
        if (cn < CC) {
            #pragma unroll
            for (int r = 0; r < 3; r++) {
                xs[1 - p][r][tid] = rx[r];
                if (tid < 2) xs[1 - p][r][tid + 256] = rx2[r];
            }
            w2[1 - p][tid] = make_float2(rw0, rw0);
            if (tid < 56 * 9 - 256)
                w2[1 - p][tid + 256] = make_float2(rw1, rw1);
        }
        __syncthreads();
        p ^= 1;
    }

    // epilogue
    size_t rowbase = ((size_t)(b * HH + h) * WW) * NOFF;
    #pragma unroll
    for (int j = 0; j < 7; j++) {
        int oc = ocg * 7 + j;
        if (oc < NOFF) {
            float bias = __ldg(&boff[oc]);
            #pragma unroll
            for (int pr = 0; pr < 4; pr++) {
                float lo, hi;
                UNPACK2(lo, hi, acc2[j][pr]);
                g_off[rowbase + (size_t)(px0 + 2 * pr) * NOFF + oc]     = lo + bias;
                g_off[rowbase + (size_t)(px0 + 2 * pr + 1) * NOFF + oc] = hi + bias;
            }
        }
    }
}

// ---------------- 4) main: pipelined gather + FFMA2 einsum -------------------
__global__ __launch_bounds__(256)
void main_kernel(float* __restrict__ out) {
    extern __shared__ float sm[];
    float* sS   = sm;                       // 2 * PX * SSTR
    float* sW   = sm + 2 * PX * SSTR;       // 2 * 4096
    float* sOff = sW + 2 * 4096;            // 64*54

    int bh = blockIdx.y;
    int b  = bh / HH, h = bh % HH;
    int w0 = blockIdx.x * PX;
    int tid = threadIdx.x;

    int s_px = tid >> 2;          // sampler pixel
    int q    = tid & 3;           // quad lane -> owns f4 chunks q, q+4, q+8, q+12
    int pxg  = tid >> 4;          // einsum: 16 px-groups of 4
    int ocg  = tid & 15;          // einsum: 16 oo-groups of 4

    const float* xTb = g_xT + (size_t)b * HH * WW * CC;

    // ---- prologue: offsets + sW[0] ----
    {
        size_t base = ((size_t)(b * HH + h) * WW + w0) * NOFF;
        for (int t = tid; t < PX * NOFF; t += 256)
            sOff[t] = g_off[base + t];
        const float4* src = (const float4*)g_weff;
        float4* dst = (float4*)sW;
        #pragma unroll
        for (int j = 0; j < 4; j++) dst[tid + j * 256] = src[tid + j * 256];
    }
    __syncthreads();

    ull acc2[4][2];
    #pragma unroll
    for (int pp = 0; pp < 4; pp++) { acc2[pp][0] = 0ull; acc2[pp][1] = 0ull; }

    float4 v[16];
    float  cw[4];

    // ---- gather issue for tap 0 ----
    {
        const int i = 0, k = 0, d = 1;
        float dy = sOff[s_px * NOFF + i * 18 + 2 * k];
        float dx = sOff[s_px * NOFF + i * 18 + 2 * k + 1];
        float ys = (float)h + (float)((k / 3 - 1) * d) + dy;
        float xs = (float)(w0 + s_px) + (float)((k % 3 - 1) * d) + dx;
        float y0f = floorf(ys), x0f = floorf(xs);
        float wy1 = ys - y0f, wx1 = xs - x0f, wy0 = 1.f - wy1, wx0 = 1.f - wx1;
        float y1f = y0f + 1.f, x1f = x0f + 1.f;
        float vy0 = (y0f >= 0.f && y0f <= 255.f) ? 1.f : 0.f;
        float vy1 = (y1f >= 0.f && y1f <= 255.f) ? 1.f : 0.f;
        float vx0 = (x0f >= 0.f && x0f <= 255.f) ? 1.f : 0.f;
        float vx1 = (x1f >= 0.f && x1f <= 255.f) ? 1.f : 0.f;
        int iy0 = (int)fminf(fmaxf(y0f, 0.f), 255.f);
        int iy1 = (int)fminf(fmaxf(y1f, 0.f), 255.f);
        int ix0 = (int)fminf(fmaxf(x0f, 0.f), 255.f);
        int ix1 = (int)fminf(fmaxf(x1f, 0.f), 255.f);
        cw[0] = wy0 * wx0 * vy0 * vx0;
        cw[1] = wy0 * wx1 * vy0 * vx1;
        cw[2] = wy1 * wx0 * vy1 * vx0;
        cw[3] = wy1 * wx1 * vy1 * vx1;
        const float4* p0 = (const float4*)(xTb + ((size_t)iy0 * WW + ix0) * CC);
        const float4* p1 = (const float4*)(xTb + ((size_t)iy0 * WW + ix1) * CC);
        const float4* p2 = (const float4*)(xTb + ((size_t)iy1 * WW + ix0) * CC);
        const float4* p3 = (const float4*)(xTb + ((size_t)iy1 * WW + ix1) * CC);
        #pragma unroll
        for (int j4 = 0; j4 < 4; j4++) {
            int fidx = q + 4 * j4;
            v[0 + j4]  = __ldg(p0 + fidx);
            v[4 + j4]  = __ldg(p1 + fidx);
            v[8 + j4]  = __ldg(p2 + fidx);
            v[12 + j4] = __ldg(p3 + fidx);
        }
    }

    int p = 0;
    for (int tap = 0; tap < ND * KK; tap++) {
        float* sSp = sS + p * (PX * SSTR);
        float* sWp = sW + p * 4096;

        // combine prefetched gather -> sS[p]
        #pragma unroll
        for (int j4 = 0; j4 < 4; j4++) {
            int fidx = q + 4 * j4;
            float4 a = v[j4], bb = v[4 + j4], c = v[8 + j4], dd = v[12 + j4];
            float4 r;
            r.x = cw[0]*a.x + cw[1]*bb.x + cw[2]*c.x + cw[3]*dd.x;
            r.y = cw[0]*a.y + cw[1]*bb.y + cw[2]*c.y + cw[3]*dd.y;
            r.z = cw[0]*a.z + cw[1]*bb.z + cw[2]*c.z + cw[3]*dd.z;
            r.w = cw[0]*a.w + cw[1]*bb.w + cw[2]*c.w + cw[3]*dd.w;
            *(float4*)&sSp[s_px * SSTR + fidx * 4] = r;
        }
        __syncthreads();

        // issue gather for tap+1 + stage sW[1-p]
        if (tap + 1 < ND * KK) {
            int tn = tap + 1;
            int i = tn / KK, k = tn % KK;
            int d = 1 << i;
            float dy = sOff[s_px * NOFF + i * 18 + 2 * k];
            float dx = sOff[s_px * NOFF + i * 18 + 2 * k + 1];
            float ys = (float)h + (float)((k / 3 - 1) * d) + dy;
            float xs = (float)(w0 + s_px) + (float)((k % 3 - 1) * d) + dx;
            float y0f = floorf(ys), x0f = floorf(xs);
            float wy1 = ys - y0f, wx1 = xs - x0f, wy0 = 1.f - wy1, wx0 = 1.f - wx1;
            float y1f = y0f + 1.f, x1f = x0f + 1.f;
            float vy0 = (y0f >= 0.f && y0f <= 255.f) ? 1.f : 0.f;
            float vy1 = (y1f >= 0.f && y1f <= 255.f) ? 1.f : 0.f;
            float vx0 = (x0f >= 0.f && x0f <= 255.f) ? 1.f : 0.f;
            float vx1 = (x1f >= 0.f && x1f <= 255.f) ? 1.f : 0.f;
            int iy0 = (int)fminf(fmaxf(y0f, 0.f), 255.f);
            int iy1 = (int)fminf(fmaxf(y1f, 0.f), 255.f);
            int ix0 = (int)fminf(fmaxf(x0f, 0.f), 255.f);
            int ix1 = (int)fminf(fmaxf(x1f, 0.f), 255.f);
            cw[0] = wy0 * wx0 * vy0 * vx0;
            cw[1] = wy0 * wx1 * vy0 * vx1;
            cw[2] = wy1 * wx0 * vy1 * vx0;
            cw[3] = wy1 * wx1 * vy1 * vx1;
            const float4* p0 = (const float4*)(xTb + ((size_t)iy0 * WW + ix0) * CC);
            const float4* p1 = (const float4*)(xTb + ((size_t)iy0 * WW + ix1) * CC);
            const float4* p2 = (const float4*)(xTb + ((size_t)iy1 * WW + ix0) * CC);
            const float4* p3 = (const float4*)(xTb + ((size_t)iy1 * WW + ix1) * CC);
            #pragma unroll
            for (int j4 = 0; j4 < 4; j4++) {
                int fidx = q + 4 * j4;
                v[0 + j4]  = __ldg(p0 + fidx);
                v[4 + j4]  = __ldg(p1 + fidx);
                v[8 + j4]  = __ldg(p2 + fidx);
                v[12 + j4] = __ldg(p3 + fidx);
            }
            // stage next Weff tile
            const float4* src = (const float4*)(g_weff + (size_t)tn * 4096);
            float4* dst = (float4*)(sW + (1 - p) * 4096);
            #pragma unroll
            for (int j = 0; j < 4; j++) dst[tid + j * 256] = src[tid + j * 256];
        }

        // einsum: acc[px][oo] += sS[px,c] * sW[c,oo]   (FFMA2 over oo pairs)
        #pragma unroll
        for (int c0 = 0; c0 < CC; c0 += 4) {
            float sa[4][4];
            #pragma unroll
            for (int pp = 0; pp < 4; pp++) {
                float4 t = *(const float4*)&sSp[(pxg * 4 + pp) * SSTR + c0];
                sa[pp][0] = t.x; sa[pp][1] = t.y; sa[pp][2] = t.z; sa[pp][3] = t.w;
            }
            #pragma unroll
            for (int cc = 0; cc < 4; cc++) {
                const ull* wp = (const ull*)&sWp[(c0 + cc) * CC + ocg * 4];
                ull wlo = wp[0], whi = wp[1];
                #pragma unroll
                for (int pp = 0; pp < 4; pp++) {
                    ull sd;
                    PACK2(sd, sa[pp][cc], sa[pp][cc]);
                    FMA2(acc2[pp][0], sd, wlo, acc2[pp][0]);
                    FMA2(acc2[pp][1], sd, whi, acc2[pp][1]);
                }
            }
        }
        p ^= 1;
    }

    // ---- epilogue: smem transpose then coalesced stores ----
    __syncthreads();
    float* sOut = sS;   // 64 oo x 64 px
    #pragma unroll
    for (int pp = 0; pp < 4; pp++) {
        float lo, hi;
        UNPACK2(lo, hi, acc2[pp][0]);
        sOut[(ocg * 4 + 0) * PX + pxg * 4 + pp] = lo;
        sOut[(ocg * 4 + 1) * PX + pxg * 4 + pp] = hi;
        UNPACK2(lo, hi, acc2[pp][1]);
        sOut[(ocg * 4 + 2) * PX + pxg * 4 + pp] = lo;
        sOut[(ocg * 4 + 3) * PX + pxg * 4 + pp] = hi;
    }
    __syncthreads();
    {
        int row = tid >> 2;           // oo
        int f0  = (tid & 3);          // f4 chunk
        float4* op = (float4*)(out + (((size_t)(b * CC + row) * HH + h) * WW + w0));
        const float4* sp = (const float4*)(sOut + row * PX);
        #pragma unroll
        for (int j = 0; j < 4; j++) op[f0 + j * 4] = sp[f0 + j * 4];
    }
}

// ---------------- launch ------------------------------------------------------
extern "C" void kernel_launch(void* const* d_in, const int* in_sizes, int n_in,
                              void* d_out, int out_size) {
    const float* x     = (const float*)d_in[0];
    const float* Woff  = (const float*)d_in[1];
    const float* boff  = (const float*)d_in[2];
    const float* Wd    = (const float*)d_in[3];
    const float* Wfuse = (const float*)d_in[4];
    float* out = (float*)d_out;

    static int smem_set = 0;
    int smem_bytes = (2 * PX * SSTR + 2 * 4096 + PX * NOFF) * 4;
    if (!smem_set) {
        cudaFuncSetAttribute(main_kernel,
                             cudaFuncAttributeMaxDynamicSharedMemorySize, smem_bytes);
        smem_set = 1;
    }

    offconv_kernel<<<BB * HH, 256>>>(x, Woff, boff);
    transpose_kernel<<<dim3(WW / 32, CC / 32, BB * HH), dim3(32, 8)>>>(x);
    weff_kernel<<<(ND * KK * CC * CC + 255) / 256, 256>>>(Wd, Wfuse);
    main_kernel<<<dim3(WW / PX, BB * HH), 256, smem_bytes>>>(out);
}

// round 4
// speedup vs baseline: 1.4412x; 1.2051x over previous
#include <cuda_runtime.h>
#include <cstdint>

#define BB   2
#define CC   64
#define HH   256
#define WW   256
#define KK   9
#define ND   3
#define NOFF 54
#define TPX  128         // pixels per main-kernel block
#define SSTR 68          // padded float stride of sS / sW rows

typedef unsigned long long ull;
typedef unsigned int u32;

#define FMA2(d, a, b, c) asm("fma.rn.f32x2 %0, %1, %2, %3;" : "=l"(d) : "l"(a), "l"(b), "l"(c))
#define PACK2(d, lo, hi) asm("mov.b64 %0, {%1, %2};" : "=l"(d) : "f"(lo), "f"(hi))
#define UNPACK2(lo, hi, s) asm("mov.b64 {%0, %1}, %2;" : "=f"(lo), "=f"(hi) : "l"(s))

__device__ __forceinline__ u32 f2tf32(float f) {
    u32 r;
    asm("cvt.rna.tf32.f32 %0, %1;" : "=r"(r) : "f"(f));
    return r;
}

// m16n8k8 tf32 mma (sm_80 baseline PTX -> legacy HMMA on sm_103)
__device__ __forceinline__ void mma_tf32(float& c0, float& c1, float& c2, float& c3,
                                         u32 a0, u32 a1, u32 a2, u32 a3,
                                         u32 b0, u32 b1) {
    asm("mma.sync.aligned.m16n8k8.row.col.f32.tf32.tf32.f32 "
        "{%0,%1,%2,%3}, {%4,%5,%6,%7}, {%8,%9}, {%0,%1,%2,%3};"
        : "+f"(c0), "+f"(c1), "+f"(c2), "+f"(c3)
        : "r"(a0), "r"(a1), "r"(a2), "r"(a3), "r"(b0), "r"(b1));
}

// ---------------- scratch ----------------------------------------------------
__device__ float g_xT[(size_t)BB * HH * WW * CC];            // NHWC x
__device__ float g_offT[(size_t)BB * HH * NOFF * WW];        // offsets (bh, ch, w)
__device__ u32  g_weffT[(size_t)ND * KK * CC * CC];          // tf32 bits, [tap][oo][perm(c)]

// ---------------- 1) transpose x -> NHWC -------------------------------------
__global__ void transpose_kernel(const float* __restrict__ x) {
    __shared__ float tile[32][33];
    int bh = blockIdx.z;
    int b  = bh / HH, h = bh % HH;
    int w0 = blockIdx.x * 32;
    int c0 = blockIdx.y * 32;
    int tx = threadIdx.x, ty = threadIdx.y;

    #pragma unroll
    for (int j = 0; j < 4; j++) {
        int c = c0 + ty + j * 8;
        tile[ty + j * 8][tx] = x[(((size_t)b * CC + c) * HH + h) * WW + (w0 + tx)];
    }
    __syncthreads();
    #pragma unroll
    for (int j = 0; j < 4; j++) {
        int w = w0 + ty + j * 8;
        g_xT[(((size_t)b * HH + h) * WW + w) * CC + (c0 + tx)] = tile[tx][ty + j * 8];
    }
}

// ---------------- 2) Weff -> permuted tf32 B tiles ----------------------------
// g_weffT[tap][oo][(c&3)*16 + (c>>2)]
__global__ void weff_kernel(const float* __restrict__ Wd,
                            const float* __restrict__ Wfuse) {
    int idx = blockIdx.x * 256 + threadIdx.x;
    if (idx >= ND * KK * CC * CC) return;
    int oo = idx % CC;
    int c  = (idx / CC) % CC;
    int k  = (idx / (CC * CC)) % KK;
    int i  = idx / (CC * CC * KK);
    float acc = 0.f;
    #pragma unroll 8
    for (int o = 0; o < CC; o++) {
        acc = fmaf(Wfuse[oo * (ND * CC) + i * CC + o],
                   Wd[(((size_t)(i * CC + o) * CC + c) * KK) + k], acc);
    }
    int tap = i * KK + k;
    int perm = (c & 3) * 16 + (c >> 2);
    g_weffT[(size_t)tap * CC * CC + oo * CC + perm] = f2tf32(acc);
}

// ---------------- 3) offset conv (FFMA2, transposed epilogue) ----------------
__global__ __launch_bounds__(256)
void offconv_kernel(const float* __restrict__ x,
                    const float* __restrict__ Woff,
                    const float* __restrict__ boff) {
    __shared__ float xs[2][3][264];
    __shared__ float2 w2[2][56 * 9];

    int bh = blockIdx.x;
    int b  = bh / HH, h = bh % HH;
    int tid = threadIdx.x;
    int ocg = tid & 7;
    int pxg = tid >> 3;
    int px0 = pxg * 8;

    const float* xb = x + (size_t)b * CC * HH * WW;

    ull acc2[7][4];
    #pragma unroll
    for (int j = 0; j < 7; j++)
        #pragma unroll
        for (int pr = 0; pr < 4; pr++) acc2[j][pr] = 0ull;

    {
        #pragma unroll
        for (int r = 0; r < 3; r++) {
            int yy = h - 1 + r;
            int xx = tid - 1;
            float v = 0.f;
            if (yy >= 0 && yy < HH && xx >= 0)
                v = xb[((size_t)0 * HH + yy) * WW + xx];
            xs[0][r][tid] = v;
            if (tid < 2) {
                int xx2 = tid + 255;
                float v2 = 0.f;
                if (yy >= 0 && yy < HH && xx2 < WW)
                    v2 = xb[((size_t)0 * HH + yy) * WW + xx2];
                xs[0][r][tid + 256] = v2;
            }
        }
        for (int t = tid; t < 56 * 9; t += 256) {
            int oc = t / 9, k = t % 9;
            float wv = (oc < NOFF) ? Woff[(size_t)oc * CC * KK + 0 * KK + k] : 0.f;
            w2[0][t] = make_float2(wv, wv);
        }
    }
    __syncthreads();

    int p = 0;
    for (int c = 0; c < CC; c++) {
        float rx[3], rx2[3], rw0 = 0.f, rw1 = 0.f;
        int cn = c + 1;
        if (cn < CC) {
            #pragma unroll
            for (int r = 0; r < 3; r++) {
                int yy = h - 1 + r;
                int xx = tid - 1;
                rx[r] = 0.f; rx2[r] = 0.f;
                if (yy >= 0 && yy < HH && xx >= 0)
                    rx[r] = xb[((size_t)cn * HH + yy) * WW + xx];
                if (tid < 2) {
                    int xx2 = tid + 255;
                    if (yy >= 0 && yy < HH && xx2 < WW)
                        rx2[r] = xb[((size_t)cn * HH + yy) * WW + xx2];
                }
            }
            {
                int t = tid;
                int oc = t / 9, k = t % 9;
                rw0 = (oc < NOFF) ? Woff[(size_t)oc * CC * KK + (size_t)cn * KK + k] : 0.f;
                if (tid < 56 * 9 - 256) {
                    int t2 = tid + 256;
                    int oc2 = t2 / 9, k2 = t2 % 9;
                    rw1 = (oc2 < NOFF) ? Woff[(size_t)oc2 * CC * KK + (size_t)cn * KK + k2] : 0.f;
                }
            }
        }

        #pragma unroll
        for (int ky = 0; ky < 3; ky++) {
            float xv[10];
            #pragma unroll
            for (int jj = 0; jj < 10; jj++) xv[jj] = xs[p][ky][px0 + jj];
            ull xp[9];
            #pragma unroll
            for (int m = 0; m < 9; m++) PACK2(xp[m], xv[m], xv[m + 1]);

            #pragma unroll
            for (int j = 0; j < 7; j++) {
                #pragma unroll
                for (int kx = 0; kx < 3; kx++) {
                    ull wd = *(const ull*)&w2[p][(ocg * 7 + j) * 9 + ky * 3 + kx];
                    #pragma unroll
                    for (int pr = 0; pr < 4; pr++)
                        FMA2(acc2[j][pr], xp[2 * pr + kx], wd, acc2[j][pr]);
                }
            }
        }

        if (cn < CC) {
            #pragma unroll
            for (int r = 0; r < 3; r++) {
                xs[1 - p][r][tid] = rx[r];
                if (tid < 2) xs[1 - p][r][tid + 256] = rx2[r];
            }
            w2[1 - p][tid] = make_float2(rw0, rw0);
            if (tid < 56 * 9 - 256)
                w2[1 - p][tid + 256] = make_float2(rw1, rw1);
        }
        __syncthreads();
        p ^= 1;
    }

    // epilogue -> transposed layout g_offT[bh][oc][w]
    #pragma unroll
    for (int j = 0; j < 7; j++) {
        int oc = ocg * 7 + j;
        if (oc < NOFF) {
            float bias = __ldg(&boff[oc]);
            size_t base = ((size_t)bh * NOFF + oc) * WW;
            #pragma unroll
            for (int pr = 0; pr < 4; pr++) {
                float lo, hi;
                UNPACK2(lo, hi, acc2[j][pr]);
                *(float2*)&g_offT[base + px0 + 2 * pr] = make_float2(lo + bias, hi + bias);
            }
        }
    }
}

// ---------------- 4) main: gather + mma.sync tf32 einsum ---------------------
// smem: sS 128x68 floats (34816B), sW 2 x 64x68 floats (34816B)  -> 69632B
__global__ __launch_bounds__(512, 1)
void main_kernel(float* __restrict__ out) {
    extern __shared__ float sm[];
    float* sS = sm;                          // [px][perm(c)] stride SSTR
    float* sW = sm + TPX * SSTR;             // 2 buffers [oo][perm(c)] stride SSTR

    int bh = blockIdx.y;
    int b  = bh / HH, h = bh % HH;
    int w0 = blockIdx.x * TPX;
    int tid = threadIdx.x;
    int lane = tid & 31, wid = tid >> 5;

    int s_px = tid >> 2;          // sampler pixel 0..127
    int q    = tid & 3;           // quad lane
    int warp_m = wid >> 1;        // 8 m-tiles of 16 px
    int warp_n = wid & 1;         // 2 n-tiles of 32 oo
    int lg = lane >> 2;           // group id 0..7
    int le = lane & 3;            // thread-in-group

    const float* xTb  = g_xT + (size_t)b * HH * WW * CC;
    const float* offb = g_offT + (size_t)bh * NOFF * WW + w0;

    float acc[4][4];
    #pragma unroll
    for (int nt = 0; nt < 4; nt++)
        #pragma unroll
        for (int e = 0; e < 4; e++) acc[nt][e] = 0.f;

    float4 v[16];
    float  cw[4];

    // ---- gather prefetch (shared by prologue + steady state) ----
    auto prefetch = [&](int tap) {
        int i = tap / KK, k = tap - i * KK;
        int d = 1 << i;
        float dy = __ldg(offb + (size_t)(i * 18 + 2 * k) * WW + s_px);
        float dx = __ldg(offb + (size_t)(i * 18 + 2 * k + 1) * WW + s_px);
        float ys = (float)h + (float)((k / 3 - 1) * d) + dy;
        float xsf = (float)(w0 + s_px) + (float)((k % 3 - 1) * d) + dx;
        float y0f = floorf(ys), x0f = floorf(xsf);
        float wy1 = ys - y0f, wx1 = xsf - x0f, wy0 = 1.f - wy1, wx0 = 1.f - wx1;
        float y1f = y0f + 1.f, x1f = x0f + 1.f;
        float vy0 = (y0f >= 0.f && y0f <= 255.f) ? 1.f : 0.f;
        float vy1 = (y1f >= 0.f && y1f <= 255.f) ? 1.f : 0.f;
        float vx0 = (x0f >= 0.f && x0f <= 255.f) ? 1.f : 0.f;
        float vx1 = (x1f >= 0.f && x1f <= 255.f) ? 1.f : 0.f;
        int iy0 = (int)fminf(fmaxf(y0f, 0.f), 255.f);
        int iy1 = (int)fminf(fmaxf(y1f, 0.f), 255.f);
        int ix0 = (int)fminf(fmaxf(x0f, 0.f), 255.f);
        int ix1 = (int)fminf(fmaxf(x1f, 0.f), 255.f);
        cw[0] = wy0 * wx0 * vy0 * vx0;
        cw[1] = wy0 * wx1 * vy0 * vx1;
        cw[2] = wy1 * wx0 * vy1 * vx0;
        cw[3] = wy1 * wx1 * vy1 * vx1;
        const float4* p0 = (const float4*)(xTb + ((size_t)iy0 * WW + ix0) * CC);
        const float4* p1 = (const float4*)(xTb + ((size_t)iy0 * WW + ix1) * CC);
        const float4* p2 = (const float4*)(xTb + ((size_t)iy1 * WW + ix0) * CC);
        const float4* p3 = (const float4*)(xTb + ((size_t)iy1 * WW + ix1) * CC);
        #pragma unroll
        for (int j4 = 0; j4 < 4; j4++) {
            int fidx = 4 * j4 + q;
            v[j4]      = __ldg(p0 + fidx);
            v[4 + j4]  = __ldg(p1 + fidx);
            v[8 + j4]  = __ldg(p2 + fidx);
            v[12 + j4] = __ldg(p3 + fidx);
        }
    };

    auto stageW = [&](int tap, int buf) {
        const float4* src = (const float4*)(g_weffT + (size_t)tap * CC * CC);
        float4* dst = (float4*)(sW + buf * (CC * SSTR));
        #pragma unroll
        for (int f0 = tid; f0 < 1024; f0 += 512) {
            float4 t = __ldg(src + f0);
            dst[(f0 >> 4) * 17 + (f0 & 15)] = t;   // [oo][perm] stride 17 f4
        }
    };

    // ---- prologue ----
    prefetch(0);
    stageW(0, 0);

    for (int tap = 0; tap < ND * KK; tap++) {
        int p = tap & 1;

        // combine prefetched gather -> sS (permuted layout, tf32 bits)
        u32* sSu = (u32*)sS;
        #pragma unroll
        for (int j4 = 0; j4 < 4; j4++) {
            float4 a = v[j4], bb = v[4 + j4], c2 = v[8 + j4], dd = v[12 + j4];
            int base = s_px * SSTR + 4 * j4 + q;
            sSu[base]      = f2tf32(cw[0]*a.x + cw[1]*bb.x + cw[2]*c2.x + cw[3]*dd.x);
            sSu[base + 16] = f2tf32(cw[0]*a.y + cw[1]*bb.y + cw[2]*c2.y + cw[3]*dd.y);
            sSu[base + 32] = f2tf32(cw[0]*a.z + cw[1]*bb.z + cw[2]*c2.z + cw[3]*dd.z);
            sSu[base + 48] = f2tf32(cw[0]*a.w + cw[1]*bb.w + cw[2]*c2.w + cw[3]*dd.w);
        }

        // stage next tap's weights into the other buffer
        if (tap + 1 < ND * KK) stageW(tap + 1, 1 - p);

        __syncthreads();   // sS + sW[p] visible

        // prefetch gather for next tap (latency covered by mma below)
        if (tap + 1 < ND * KK) prefetch(tap + 1);

        // einsum via mma.sync tf32: 16px x 32oo per warp
        {
            const float* sWp = sW + p * (CC * SSTR);
            int arow = warp_m * 16 + lg;
            int bbase = warp_n * 32 + lg;
            #pragma unroll
            for (int s2 = 0; s2 < 4; s2++) {
                int cofs = le * 16 + 4 * s2;
                float4 alo = *(const float4*)&sS[arow * SSTR + cofs];
                float4 ahi = *(const float4*)&sS[(arow + 8) * SSTR + cofs];
                #pragma unroll
                for (int nt = 0; nt < 4; nt++) {
                    float4 bv = *(const float4*)&sWp[(bbase + nt * 8) * SSTR + cofs];
                    mma_tf32(acc[nt][0], acc[nt][1], acc[nt][2], acc[nt][3],
                             __float_as_uint(alo.x), __float_as_uint(ahi.x),
                             __float_as_uint(alo.y), __float_as_uint(ahi.y),
                             __float_as_uint(bv.x),  __float_as_uint(bv.y));
                    mma_tf32(acc[nt][0], acc[nt][1], acc[nt][2], acc[nt][3],
                             __float_as_uint(alo.z), __float_as_uint(ahi.z),
                             __float_as_uint(alo.w), __float_as_uint(ahi.w),
                             __float_as_uint(bv.z),  __float_as_uint(bv.w));
                }
            }
        }

        __syncthreads();   // all warps done with sS before next combine
    }

    // ---- epilogue: frags -> smem [oo][px] -> coalesced stores ----
    float* sOut = sm;    // 64 x 128 floats = 32KB, fits in sS+sW region
    {
        int px0 = warp_m * 16 + lg;
        #pragma unroll
        for (int nt = 0; nt < 4; nt++) {
            int oo = warp_n * 32 + nt * 8 + 2 * le;
            sOut[oo * TPX + px0]             = acc[nt][0];
            sOut[(oo + 1) * TPX + px0]       = acc[nt][1];
            sOut[oo * TPX + px0 + 8]         = acc[nt][2];
            sOut[(oo + 1) * TPX + px0 + 8]   = acc[nt][3];
        }
    }
    __syncthreads();
    {
        int row = tid >> 3;          // oo
        int f0  = tid & 7;
        float4* op = (float4*)(out + (((size_t)(b * CC + row) * HH + h) * WW + w0));
        const float4* sp = (const float4*)(sOut + row * TPX);
        #pragma unroll
        for (int j = 0; j < 4; j++) op[f0 + j * 8] = sp[f0 + j * 8];
    }
}

// ---------------- launch ------------------------------------------------------
extern "C" void kernel_launch(void* const* d_in, const int* in_sizes, int n_in,
                              void* d_out, int out_size) {
    const float* x     = (const float*)d_in[0];
    const float* Woff  = (const float*)d_in[1];
    const float* boff  = (const float*)d_in[2];
    const float* Wd    = (const float*)d_in[3];
    const float* Wfuse = (const float*)d_in[4];
    float* out = (float*)d_out;

    int smem_bytes = (TPX * SSTR + 2 * CC * SSTR) * 4;
    static int smem_set = 0;
    if (!smem_set) {
        cudaFuncSetAttribute(main_kernel,
                             cudaFuncAttributeMaxDynamicSharedMemorySize, smem_bytes);
        smem_set = 1;
    }

    offconv_kernel<<<BB * HH, 256>>>(x, Woff, boff);
    transpose_kernel<<<dim3(WW / 32, CC / 32, BB * HH), dim3(32, 8)>>>(x);
    weff_kernel<<<(ND * KK * CC * CC + 255) / 256, 256>>>(Wd, Wfuse);
    main_kernel<<<dim3(WW / TPX, BB * HH), 512, smem_bytes>>>(out);
}

// round 5
// speedup vs baseline: 1.7786x; 1.2341x over previous
#include <cuda_runtime.h>
#include <cstdint>

#define BB   2
#define CC   64
#define HH   256
#define WW   256
#define KK   9
#define ND   3
#define NOFF 54
#define TPX  128         // pixels per main-kernel block
#define SSTR 68          // padded float stride of sS / sW rows

typedef unsigned long long ull;
typedef unsigned int u32;

#define FMA2(d, a, b, c) asm("fma.rn.f32x2 %0, %1, %2, %3;" : "=l"(d) : "l"(a), "l"(b), "l"(c))
#define PACK2(d, lo, hi) asm("mov.b64 %0, {%1, %2};" : "=l"(d) : "f"(lo), "f"(hi))
#define UNPACK2(lo, hi, s) asm("mov.b64 {%0, %1}, %2;" : "=f"(lo), "=f"(hi) : "l"(s))

__device__ __forceinline__ u32 f2tf32(float f) {
    u32 r;
    asm("cvt.rna.tf32.f32 %0, %1;" : "=r"(r) : "f"(f));
    return r;
}

// m16n8k8 tf32 mma (sm_80 baseline PTX -> legacy HMMA on sm_103)
__device__ __forceinline__ void mma_tf32(float* c,
                                         u32 a0, u32 a1, u32 a2, u32 a3,
                                         u32 b0, u32 b1) {
    asm("mma.sync.aligned.m16n8k8.row.col.f32.tf32.tf32.f32 "
        "{%0,%1,%2,%3}, {%4,%5,%6,%7}, {%8,%9}, {%0,%1,%2,%3};"
        : "+f"(c[0]), "+f"(c[1]), "+f"(c[2]), "+f"(c[3])
        : "r"(a0), "r"(a1), "r"(a2), "r"(a3), "r"(b0), "r"(b1));
}

// ---------------- scratch ----------------------------------------------------
// g_xT: channel-PERMUTED NHWC: position p holds channel c = 4*(p&15) + (p>>4)
__device__ float g_xT[(size_t)BB * HH * WW * CC];
__device__ float g_offT[(size_t)BB * HH * NOFF * WW];        // offsets (bh, ch, w)
__device__ u32  g_weffT[(size_t)ND * KK * CC * CC];          // tf32, [tap][oo][perm(c)]

// ---------------- 1) transpose x -> permuted NHWC -----------------------------
__global__ void transpose_kernel(const float* __restrict__ x) {
    __shared__ float tile[32][33];
    int bh = blockIdx.z;
    int b  = bh / HH, h = bh % HH;
    int w0 = blockIdx.x * 32;
    int c0 = blockIdx.y * 32;
    int tx = threadIdx.x, ty = threadIdx.y;

    #pragma unroll
    for (int j = 0; j < 4; j++) {
        int c = c0 + ty + j * 8;
        tile[ty + j * 8][tx] = x[(((size_t)b * CC + c) * HH + h) * WW + (w0 + tx)];
    }
    __syncthreads();
    #pragma unroll
    for (int j = 0; j < 4; j++) {
        int w = w0 + ty + j * 8;
        int c = c0 + tx;
        int pos = ((c & 3) << 4) | (c >> 2);   // perm(c)
        g_xT[(((size_t)b * HH + h) * WW + w) * CC + pos] = tile[tx][ty + j * 8];
    }
}

// ---------------- 2) Weff -> permuted tf32 B tiles ----------------------------
__global__ void weff_kernel(const float* __restrict__ Wd,
                            const float* __restrict__ Wfuse) {
    int idx = blockIdx.x * 256 + threadIdx.x;
    if (idx >= ND * KK * CC * CC) return;
    int oo = idx % CC;
    int c  = (idx / CC) % CC;
    int k  = (idx / (CC * CC)) % KK;
    int i  = idx / (CC * CC * KK);
    float acc = 0.f;
    #pragma unroll 8
    for (int o = 0; o < CC; o++) {
        acc = fmaf(Wfuse[oo * (ND * CC) + i * CC + o],
                   Wd[(((size_t)(i * CC + o) * CC + c) * KK) + k], acc);
    }
    int tap = i * KK + k;
    int perm = (c & 3) * 16 + (c >> 2);
    g_weffT[(size_t)tap * CC * CC + oo * CC + perm] = f2tf32(acc);
}

// ---------------- 3) offset conv (FFMA2, transposed epilogue) ----------------
__global__ __launch_bounds__(256)
void offconv_kernel(const float* __restrict__ x,
                    const float* __restrict__ Woff,
                    const float* __restrict__ boff) {
    __shared__ float xs[2][3][264];
    __shared__ float2 w2[2][56 * 9];

    int bh = blockIdx.x;
    int b  = bh / HH, h = bh % HH;
    int tid = threadIdx.x;
    int ocg = tid & 7;
    int pxg = tid >> 3;
    int px0 = pxg * 8;

    const float* xb = x + (size_t)b * CC * HH * WW;

    ull acc2[7][4];
    #pragma unroll
    for (int j = 0; j < 7; j++)
        #pragma unroll
        for (int pr = 0; pr < 4; pr++) acc2[j][pr] = 0ull;

    {
        #pragma unroll
        for (int r = 0; r < 3; r++) {
            int yy = h - 1 + r;
            int xx = tid - 1;
            float v = 0.f;
            if (yy >= 0 && yy < HH && xx >= 0)
                v = xb[((size_t)0 * HH + yy) * WW + xx];
            xs[0][r][tid] = v;
            if (tid < 2) {
                int xx2 = tid + 255;
                float v2 = 0.f;
                if (yy >= 0 && yy < HH && xx2 < WW)
                    v2 = xb[((size_t)0 * HH + yy) * WW + xx2];
                xs[0][r][tid + 256] = v2;
            }
        }
        for (int t = tid; t < 56 * 9; t += 256) {
            int oc = t / 9, k = t % 9;
            float wv = (oc < NOFF) ? Woff[(size_t)oc * CC * KK + 0 * KK + k] : 0.f;
            w2[0][t] = make_float2(wv, wv);
        }
    }
    __syncthreads();

    int p = 0;
    for (int c = 0; c < CC; c++) {
        float rx[3], rx2[3], rw0 = 0.f, rw1 = 0.f;
        int cn = c + 1;
        if (cn < CC) {
            #pragma unroll
            for (int r = 0; r < 3; r++) {
                int yy = h - 1 + r;
                int xx = tid - 1;
                rx[r] = 0.f; rx2[r] = 0.f;
                if (yy >= 0 && yy < HH && xx >= 0)
                    rx[r] = xb[((size_t)cn * HH + yy) * WW + xx];
                if (tid < 2) {
                    int xx2 = tid + 255;
                    if (yy >= 0 && yy < HH && xx2 < WW)
                        rx2[r] = xb[((size_t)cn * HH + yy) * WW + xx2];
                }
            }
            {
                int t = tid;
                int oc = t / 9, k = t % 9;
                rw0 = (oc < NOFF) ? Woff[(size_t)oc * CC * KK + (size_t)cn * KK + k] : 0.f;
                if (tid < 56 * 9 - 256) {
                    int t2 = tid + 256;
                    int oc2 = t2 / 9, k2 = t2 % 9;
                    rw1 = (oc2 < NOFF) ? Woff[(size_t)oc2 * CC * KK + (size_t)cn * KK + k2] : 0.f;
                }
            }
        }

        #pragma unroll
        for (int ky = 0; ky < 3; ky++) {
            float xv[10];
            #pragma unroll
            for (int jj = 0; jj < 10; jj++) xv[jj] = xs[p][ky][px0 + jj];
            ull xp[9];
            #pragma unroll
            for (int m = 0; m < 9; m++) PACK2(xp[m], xv[m], xv[m + 1]);

            #pragma unroll
            for (int j = 0; j < 7; j++) {
                #pragma unroll
                for (int kx = 0; kx < 3; kx++) {
                    ull wd = *(const ull*)&w2[p][(ocg * 7 + j) * 9 + ky * 3 + kx];
                    #pragma unroll
                    for (int pr = 0; pr < 4; pr++)
                        FMA2(acc2[j][pr], xp[2 * pr + kx], wd, acc2[j][pr]);
                }
            }
        }

        if (cn < CC) {
            #pragma unroll
            for (int r = 0; r < 3; r++) {
                xs[1 - p][r][tid] = rx[r];
                if (tid < 2) xs[1 - p][r][tid + 256] = rx2[r];
            }
            w2[1 - p][tid] = make_float2(rw0, rw0);
            if (tid < 56 * 9 - 256)
                w2[1 - p][tid + 256] = make_float2(rw1, rw1);
        }
        __syncthreads();
        p ^= 1;
    }

    #pragma unroll
    for (int j = 0; j < 7; j++) {
        int oc = ocg * 7 + j;
        if (oc < NOFF) {
            float bias = __ldg(&boff[oc]);
            size_t base = ((size_t)bh * NOFF + oc) * WW;
            #pragma unroll
            for (int pr = 0; pr < 4; pr++) {
                float lo, hi;
                UNPACK2(lo, hi, acc2[j][pr]);
                *(float2*)&g_offT[base + px0 + 2 * pr] = make_float2(lo + bias, hi + bias);
            }
        }
    }
}

// ---------------- 4) main: coalesced gather + mma.sync tf32 einsum -----------
// smem floats: sS 128*68 (34816B), sW 2*64*68 (34816B), sG 2*128*8 (8192B)
#define SMF_S   0
#define SMF_W   (TPX * SSTR)
#define SMF_G   (SMF_W + 2 * CC * SSTR)
#define SMF_TOT (SMF_G + 2 * TPX * 8)

__global__ __launch_bounds__(256, 2)
void main_kernel(float* __restrict__ out) {
    extern __shared__ float sm[];
    float* sS = sm + SMF_S;
    float* sW = sm + SMF_W;
    float* sG = sm + SMF_G;

    int bh = blockIdx.y;
    int b  = bh / HH, h = bh % HH;
    int w0 = blockIdx.x * TPX;
    int tid = threadIdx.x;
    int lane = tid & 31, wid = tid >> 5;

    int grp = tid >> 4;           // gather group 0..15 (8 px each)
    int f   = tid & 15;           // chunk lane (16B chunk f of 256B row)
    int warp_m = wid >> 1;        // 4 m-warps of 32 px
    int warp_n = wid & 1;         // 2 n-warps of 32 oo
    int lg = lane >> 2;
    int le = lane & 3;

    const char*  xTb  = (const char*)(g_xT + (size_t)b * HH * WW * CC);
    const float* offb = g_offT + (size_t)bh * NOFF * WW + w0;

    float acc[2][4][4];
    #pragma unroll
    for (int mt = 0; mt < 2; mt++)
        #pragma unroll
        for (int nt = 0; nt < 4; nt++)
            #pragma unroll
            for (int e = 0; e < 4; e++) acc[mt][nt][e] = 0.f;

    // ---- per-pixel bilinear setup -> sG[buf][px][8] (tid<128: px = tid) ----
    auto setup = [&](int tap, int buf) {
        if (tid < TPX) {
            int px = tid;
            int i = tap / KK, k = tap - i * KK;
            int d = 1 << i;
            float dy = __ldg(offb + (size_t)(i * 18 + 2 * k) * WW + px);
            float dx = __ldg(offb + (size_t)(i * 18 + 2 * k + 1) * WW + px);
            float ys  = (float)h + (float)((k / 3 - 1) * d) + dy;
            float xsf = (float)(w0 + px) + (float)((k % 3 - 1) * d) + dx;
            float y0f = floorf(ys), x0f = floorf(xsf);
            float wy1 = ys - y0f, wx1 = xsf - x0f, wy0 = 1.f - wy1, wx0 = 1.f - wx1;
            float y1f = y0f + 1.f, x1f = x0f + 1.f;
            float vy0 = (y0f >= 0.f && y0f <= 255.f) ? 1.f : 0.f;
            float vy1 = (y1f >= 0.f && y1f <= 255.f) ? 1.f : 0.f;
            float vx0 = (x0f >= 0.f && x0f <= 255.f) ? 1.f : 0.f;
            float vx1 = (x1f >= 0.f && x1f <= 255.f) ? 1.f : 0.f;
            u32 iy0 = (u32)(int)fminf(fmaxf(y0f, 0.f), 255.f);
            u32 iy1 = (u32)(int)fminf(fmaxf(y1f, 0.f), 255.f);
            u32 ix0 = (u32)(int)fminf(fmaxf(x0f, 0.f), 255.f);
            u32 ix1 = (u32)(int)fminf(fmaxf(x1f, 0.f), 255.f);
            uint4 o;
            o.x = ((iy0 * WW + ix0) * CC) * 4u;
            o.y = ((iy0 * WW + ix1) * CC) * 4u;
            o.z = ((iy1 * WW + ix0) * CC) * 4u;
            o.w = ((iy1 * WW + ix1) * CC) * 4u;
            float4 cw = make_float4(wy0 * wx0 * vy0 * vx0, wy0 * wx1 * vy0 * vx1,
                                    wy1 * wx0 * vy1 * vx0, wy1 * wx1 * vy1 * vx1);
            *(uint4*) &sG[(buf * TPX + px) * 8]     = o;
            *(float4*)&sG[(buf * TPX + px) * 8 + 4] = cw;
        }
    };

    auto stageW = [&](int tap, int buf) {
        const float4* src = (const float4*)(g_weffT + (size_t)tap * CC * CC);
        float4* dst = (float4*)(sW + buf * (CC * SSTR));
        #pragma unroll
        for (int kk2 = 0; kk2 < 4; kk2++) {
            int f0 = tid + kk2 * 256;
            float4 t = __ldg(src + f0);
            dst[(f0 >> 4) * 17 + (f0 & 15)] = t;
        }
    };

    // ---- prologue ----
    setup(0, 0);
    stageW(0, 0);
    __syncthreads();

    u32* sSu = (u32*)sS;

    for (int tap = 0; tap < ND * KK; tap++) {
        int p = tap & 1;

        // ---- gather: group handles 8 px, lane f loads 16B chunk f of each corner
        {
            const float* gp = &sG[(p * TPX + grp * 8) * 8];
            uint4  o  = *(const uint4*) (gp);
            float4 cw = *(const float4*)(gp + 4);
            float4 c0 = __ldg((const float4*)(xTb + o.x) + f);
            float4 c1 = __ldg((const float4*)(xTb + o.y) + f);
            float4 c2 = __ldg((const float4*)(xTb + o.z) + f);
            float4 c3 = __ldg((const float4*)(xTb + o.w) + f);

            #pragma unroll
            for (int j = 0; j < 8; j++) {
                uint4 no; float4 ncw;
                float4 n0, n1, n2, n3;
                if (j < 7) {
                    const float* gq = &sG[(p * TPX + grp * 8 + j + 1) * 8];
                    no  = *(const uint4*) (gq);
                    ncw = *(const float4*)(gq + 4);
                    n0 = __ldg((const float4*)(xTb + no.x) + f);
                    n1 = __ldg((const float4*)(xTb + no.y) + f);
                    n2 = __ldg((const float4*)(xTb + no.z) + f);
                    n3 = __ldg((const float4*)(xTb + no.w) + f);
                }
                uint4 r;
                r.x = f2tf32(cw.x*c0.x + cw.y*c1.x + cw.z*c2.x + cw.w*c3.x);
                r.y = f2tf32(cw.x*c0.y + cw.y*c1.y + cw.z*c2.y + cw.w*c3.y);
                r.z = f2tf32(cw.x*c0.z + cw.y*c1.z + cw.z*c2.z + cw.w*c3.z);
                r.w = f2tf32(cw.x*c0.w + cw.y*c1.w + cw.z*c2.w + cw.w*c3.w);
                *(uint4*)&sSu[(grp * 8 + j) * SSTR + 4 * f] = r;
                if (j < 7) { o = no; cw = ncw; c0 = n0; c1 = n1; c2 = n2; c3 = n3; }
            }
        }

        // ---- stage next tap (other buffers) ----
        if (tap + 1 < ND * KK) {
            setup(tap + 1, 1 - p);
            stageW(tap + 1, 1 - p);
        }

        __syncthreads();   // sS + staged buffers visible

        // ---- einsum via mma.sync tf32: 32px x 32oo per warp ----
        {
            const float* sWp = sW + p * (CC * SSTR);
            int arow = warp_m * 32 + lg;
            int brow = warp_n * 32 + lg;
            #pragma unroll
            for (int s2 = 0; s2 < 4; s2++) {
                int cofs = le * 16 + 4 * s2;
                float4 a0lo = *(const float4*)&sS[(arow)      * SSTR + cofs];
                float4 a0hi = *(const float4*)&sS[(arow + 8)  * SSTR + cofs];
                float4 a1lo = *(const float4*)&sS[(arow + 16) * SSTR + cofs];
                float4 a1hi = *(const float4*)&sS[(arow + 24) * SSTR + cofs];
                #pragma unroll
                for (int nt = 0; nt < 4; nt++) {
                    float4 bv = *(const float4*)&sWp[(brow + nt * 8) * SSTR + cofs];
                    mma_tf32(acc[0][nt],
                             __float_as_uint(a0lo.x), __float_as_uint(a0hi.x),
                             __float_as_uint(a0lo.y), __float_as_uint(a0hi.y),
                             __float_as_uint(bv.x),   __float_as_uint(bv.y));
                    mma_tf32(acc[0][nt],
                             __float_as_uint(a0lo.z), __float_as_uint(a0hi.z),
                             __float_as_uint(a0lo.w), __float_as_uint(a0hi.w),
                             __float_as_uint(bv.z),   __float_as_uint(bv.w));
                    mma_tf32(acc[1][nt],
                             __float_as_uint(a1lo.x), __float_as_uint(a1hi.x),
                             __float_as_uint(a1lo.y), __float_as_uint(a1hi.y),
                             __float_as_uint(bv.x),   __float_as_uint(bv.y));
                    mma_tf32(acc[1][nt],
                             __float_as_uint(a1lo.z), __float_as_uint(a1hi.z),
                             __float_as_uint(a1lo.w), __float_as_uint(a1hi.w),
                             __float_as_uint(bv.z),   __float_as_uint(bv.w));
                }
            }
        }

        __syncthreads();   // mma done reading sS before next gather overwrites
    }

    // ---- epilogue: frags -> smem [oo][px] -> coalesced stores ----
    float* sOut = sm;   // 64 x 128 floats = 32KB (reuses sS)
    #pragma unroll
    for (int mt = 0; mt < 2; mt++) {
        int px0 = warp_m * 32 + mt * 16 + lg;
        #pragma unroll
        for (int nt = 0; nt < 4; nt++) {
            int oo = warp_n * 32 + nt * 8 + 2 * le;
            sOut[oo * TPX + px0]           = acc[mt][nt][0];
            sOut[(oo + 1) * TPX + px0]     = acc[mt][nt][1];
            sOut[oo * TPX + px0 + 8]       = acc[mt][nt][2];
            sOut[(oo + 1) * TPX + px0 + 8] = acc[mt][nt][3];
        }
    }
    __syncthreads();
    {
        int row = tid >> 2;          // oo 0..63
        int f0  = tid & 3;
        float4* op = (float4*)(out + (((size_t)(b * CC + row) * HH + h) * WW + w0));
        const float4* sp = (const float4*)(sOut + row * TPX);
        #pragma unroll
        for (int j = 0; j < 8; j++) op[f0 + j * 4] = sp[f0 + j * 4];
    }
}

// ---------------- launch ------------------------------------------------------
extern "C" void kernel_launch(void* const* d_in, const int* in_sizes, int n_in,
                              void* d_out, int out_size) {
    const float* x     = (const float*)d_in[0];
    const float* Woff  = (const float*)d_in[1];
    const float* boff  = (const float*)d_in[2];
    const float* Wd    = (const float*)d_in[3];
    const float* Wfuse = (const float*)d_in[4];
    float* out = (float*)d_out;

    int smem_bytes = SMF_TOT * 4;
    static int smem_set = 0;
    if (!smem_set) {
        cudaFuncSetAttribute(main_kernel,
                             cudaFuncAttributeMaxDynamicSharedMemorySize, smem_bytes);
        smem_set = 1;
    }

    offconv_kernel<<<BB * HH, 256>>>(x, Woff, boff);
    transpose_kernel<<<dim3(WW / 32, CC / 32, BB * HH), dim3(32, 8)>>>(x);
    weff_kernel<<<(ND * KK * CC * CC + 255) / 256, 256>>>(Wd, Wfuse);
    main_kernel<<<dim3(WW / TPX, BB * HH), 256, smem_bytes>>>(out);
}

// round 6
// speedup vs baseline: 2.7743x; 1.5598x over previous
#include <cuda_runtime.h>
#include <cstdint>

#define BB   2
#define CC   64
#define HH   256
#define WW   256
#define KK   9
#define ND   3
#define NOFF 54
#define TPX  128         // pixels per main-kernel block
#define SSTR 68          // padded float stride of sS rows
#define OSTR 68          // padded float stride of offconv sX rows

typedef unsigned long long ull;
typedef unsigned int u32;

__device__ __forceinline__ u32 f2tf32(float f) {
    u32 r;
    asm("cvt.rna.tf32.f32 %0, %1;" : "=r"(r) : "f"(f));
    return r;
}

// m16n8k8 tf32 mma (sm_80 baseline PTX -> HMMA on sm_103)
__device__ __forceinline__ void mma_tf32(float* c,
                                         u32 a0, u32 a1, u32 a2, u32 a3,
                                         u32 b0, u32 b1) {
    asm("mma.sync.aligned.m16n8k8.row.col.f32.tf32.tf32.f32 "
        "{%0,%1,%2,%3}, {%4,%5,%6,%7}, {%8,%9}, {%0,%1,%2,%3};"
        : "+f"(c[0]), "+f"(c[1]), "+f"(c[2]), "+f"(c[3])
        : "r"(a0), "r"(a1), "r"(a2), "r"(a3), "r"(b0), "r"(b1));
}

// ---------------- scratch ----------------------------------------------------
// g_xT: channel-PERMUTED NHWC: position p holds channel c with perm(c)=(c&3)*16+(c>>2)
__device__ float g_xT[(size_t)BB * HH * WW * CC];
__device__ float g_offT[(size_t)BB * HH * NOFF * WW];   // offsets (bh, ch, w)
// fragment-ordered tf32 weights: [tap][ (((wn*4+s2)*4+nt)*8+lg)*4+le ] float4
__device__ float g_weffF[(size_t)ND * KK * CC * CC];
__device__ float g_woffF[(size_t)KK * CC * CC];         // offset-conv weights, oc padded to 64

// fragment-position helper: scalar (oo, permcol p) -> flat float index in 64x64 tile
__device__ __forceinline__ int frag_index(int oo, int p) {
    int le = p >> 4, rem = p & 15, s2 = rem >> 2, el = rem & 3;
    int wn = oo >> 5, r5 = oo & 31, nt = r5 >> 3, lg = r5 & 7;
    return ((((wn * 4 + s2) * 4 + nt) * 8 + lg) * 4 + le) * 4 + el;
}

// ---------------- 1) transpose x -> permuted NHWC -----------------------------
__global__ void transpose_kernel(const float* __restrict__ x) {
    __shared__ float tile[32][33];
    int bh = blockIdx.z;
    int b  = bh / HH, h = bh % HH;
    int w0 = blockIdx.x * 32;
    int c0 = blockIdx.y * 32;
    int tx = threadIdx.x, ty = threadIdx.y;

    #pragma unroll
    for (int j = 0; j < 4; j++) {
        int c = c0 + ty + j * 8;
        tile[ty + j * 8][tx] = x[(((size_t)b * CC + c) * HH + h) * WW + (w0 + tx)];
    }
    __syncthreads();
    #pragma unroll
    for (int j = 0; j < 4; j++) {
        int w = w0 + ty + j * 8;
        int c = c0 + tx;
        int pos = ((c & 3) << 4) | (c >> 2);
        g_xT[(((size_t)b * HH + h) * WW + w) * CC + pos] = tile[tx][ty + j * 8];
    }
}

// ---------------- 2a) Weff -> fragment-ordered tf32 ---------------------------
__global__ void weff_kernel(const float* __restrict__ Wd,
                            const float* __restrict__ Wfuse) {
    int idx = blockIdx.x * 256 + threadIdx.x;
    if (idx >= ND * KK * CC * CC) return;
    int oo = idx % CC;
    int c  = (idx / CC) % CC;
    int k  = (idx / (CC * CC)) % KK;
    int i  = idx / (CC * CC * KK);
    float acc = 0.f;
    #pragma unroll 8
    for (int o = 0; o < CC; o++) {
        acc = fmaf(Wfuse[oo * (ND * CC) + i * CC + o],
                   Wd[(((size_t)(i * CC + o) * CC + c) * KK) + k], acc);
    }
    int tap = i * KK + k;
    int p = (c & 3) * 16 + (c >> 2);
    ((u32*)g_weffF)[(size_t)tap * CC * CC + frag_index(oo, p)] = f2tf32(acc);
}

// ---------------- 2b) Woff -> fragment-ordered tf32 (oc padded to 64) ---------
__global__ void woff_kernel(const float* __restrict__ Woff) {
    int idx = blockIdx.x * 256 + threadIdx.x;
    if (idx >= KK * CC * CC) return;
    int c  = idx % CC;
    int oc = (idx / CC) % CC;
    int k  = idx / (CC * CC);
    float v = (oc < NOFF) ? Woff[(size_t)oc * CC * KK + c * KK + k] : 0.f;
    int p = (c & 3) * 16 + (c >> 2);
    ((u32*)g_woffF)[(size_t)k * CC * CC + frag_index(oc, p)] = f2tf32(v);
}

// ---------------- 3) offset conv via mma.sync (9 shifted GEMMs) ---------------
// block: 128 px of one row; smem: sX[2][130*OSTR] tf32 bits
__global__ __launch_bounds__(256, 2)
void offconv_kernel(const float* __restrict__ boff) {
    extern __shared__ u32 smo[];
    u32* sX = smo;                        // 2 * 130 * OSTR

    int bh = blockIdx.y;
    int b  = bh / HH, h = bh % HH;
    int w0 = blockIdx.x * TPX;
    int tid = threadIdx.x;
    int lane = tid & 31, wid = tid >> 5;
    int warp_m = wid >> 1;                // 4 m-warps of 32 px
    int warp_n = wid & 1;                 // 2 n-warps of 32 oc
    int lg = lane >> 2;
    int le = lane & 3;

    const float* xTrow = g_xT + (size_t)b * HH * WW * CC;

    float acc[2][4][4];
    #pragma unroll
    for (int mt = 0; mt < 2; mt++)
        #pragma unroll
        for (int nt = 0; nt < 4; nt++)
            #pragma unroll
            for (int e = 0; e < 4; e++) acc[mt][nt][e] = 0.f;

    for (int ky = 0; ky < 3; ky++) {
        int row = h + ky - 1;
        if (row < 0 || row >= HH) continue;   // uniform per block

        u32* sXp = sX + (ky & 1) * (130 * OSTR);
        // stage row segment w0-1 .. w0+128 (130 px), tf32 bits, coalesced
        {
            const float4* src = (const float4*)(xTrow + (size_t)row * WW * CC);
            for (int t = tid; t < 130 * 16; t += 256) {
                int px = t >> 4, ch = t & 15;
                int w = w0 - 1 + px;
                uint4 val = make_uint4(0u, 0u, 0u, 0u);
                if (w >= 0 && w < WW) {
                    float4 v = __ldg(src + (size_t)w * 16 + ch);
                    val.x = f2tf32(v.x); val.y = f2tf32(v.y);
                    val.z = f2tf32(v.z); val.w = f2tf32(v.w);
                }
                *(uint4*)&sXp[px * OSTR + ch * 4] = val;
            }
        }
        __syncthreads();

        #pragma unroll
        for (int kx = 0; kx < 3; kx++) {
            int k = ky * 3 + kx;
            const float4* wF = (const float4*)g_woffF + (size_t)k * 1024 + warp_n * 512;
            int abase = warp_m * 32 + kx;     // sX row = px_local + kx
            #pragma unroll
            for (int s2 = 0; s2 < 4; s2++) {
                int cofs = le * 16 + 4 * s2;
                uint4 a0lo = *(const uint4*)&sXp[(abase + lg)      * OSTR + cofs];
                uint4 a0hi = *(const uint4*)&sXp[(abase + lg + 8)  * OSTR + cofs];
                uint4 a1lo = *(const uint4*)&sXp[(abase + lg + 16) * OSTR + cofs];
                uint4 a1hi = *(const uint4*)&sXp[(abase + lg + 24) * OSTR + cofs];
                #pragma unroll
                for (int nt = 0; nt < 4; nt++) {
                    float4 bvf = __ldg(wF + (s2 * 4 + nt) * 32 + lane);
                    u32 b0 = __float_as_uint(bvf.x), b1 = __float_as_uint(bvf.y);
                    u32 b2 = __float_as_uint(bvf.z), b3 = __float_as_uint(bvf.w);
                    mma_tf32(acc[0][nt], a0lo.x, a0hi.x, a0lo.y, a0hi.y, b0, b1);
                    mma_tf32(acc[0][nt], a0lo.z, a0hi.z, a0lo.w, a0hi.w, b2, b3);
                    mma_tf32(acc[1][nt], a1lo.x, a1hi.x, a1lo.y, a1hi.y, b0, b1);
                    mma_tf32(acc[1][nt], a1lo.z, a1hi.z, a1lo.w, a1hi.w, b2, b3);
                }
            }
        }
        __syncthreads();   // mma reads done before next stage reuses buffer
    }

    // epilogue: frags(+bias) -> smem [oc][px] -> coalesced g_offT stores
    float* sOut = (float*)smo;    // 64 x 128 floats = 32KB
    __syncthreads();
    #pragma unroll
    for (int mt = 0; mt < 2; mt++) {
        int px0 = warp_m * 32 + mt * 16 + lg;
        #pragma unroll
        for (int nt = 0; nt < 4; nt++) {
            int oc = warp_n * 32 + nt * 8 + 2 * le;
            float b0 = (oc < NOFF)     ? __ldg(&boff[oc])     : 0.f;
            float b1 = (oc + 1 < NOFF) ? __ldg(&boff[oc + 1]) : 0.f;
            sOut[oc * TPX + px0]           = acc[mt][nt][0] + b0;
            sOut[(oc + 1) * TPX + px0]     = acc[mt][nt][1] + b1;
            sOut[oc * TPX + px0 + 8]       = acc[mt][nt][2] + b0;
            sOut[(oc + 1) * TPX + px0 + 8] = acc[mt][nt][3] + b1;
        }
    }
    __syncthreads();
    {
        int oc = tid >> 2;           // 0..63
        int f0 = tid & 3;
        if (oc < NOFF) {
            float4* op = (float4*)(g_offT + ((size_t)bh * NOFF + oc) * WW + w0);
            const float4* sp = (const float4*)(sOut + oc * TPX);
            #pragma unroll
            for (int j = 0; j < 8; j++) op[f0 + j * 4] = sp[f0 + j * 4];
        }
    }
}

// ---------------- 4) main: coalesced gather + mma.sync tf32 einsum -----------
// smem floats: sS 128*68 (34816B), sG 2*128*8 (8192B)
#define SMF_S   0
#define SMF_G   (TPX * SSTR)
#define SMF_TOT (SMF_G + 2 * TPX * 8)

__global__ __launch_bounds__(256, 2)
void main_kernel(float* __restrict__ out) {
    extern __shared__ float sm[];
    float* sS = sm + SMF_S;
    float* sG = sm + SMF_G;

    int bh = blockIdx.y;
    int b  = bh / HH, h = bh % HH;
    int w0 = blockIdx.x * TPX;
    int tid = threadIdx.x;
    int lane = tid & 31, wid = tid >> 5;

    int grp = tid >> 4;           // gather group 0..15 (8 px each)
    int f   = tid & 15;           // chunk lane
    int warp_m = wid >> 1;
    int warp_n = wid & 1;
    int lg = lane >> 2;
    int le = lane & 3;

    const char*  xTb  = (const char*)(g_xT + (size_t)b * HH * WW * CC);
    const float* offb = g_offT + (size_t)bh * NOFF * WW + w0;

    float acc[2][4][4];
    #pragma unroll
    for (int mt = 0; mt < 2; mt++)
        #pragma unroll
        for (int nt = 0; nt < 4; nt++)
            #pragma unroll
            for (int e = 0; e < 4; e++) acc[mt][nt][e] = 0.f;

    auto setup = [&](int tap, int buf) {
        if (tid < TPX) {
            int px = tid;
            int i = tap / KK, k = tap - i * KK;
            int d = 1 << i;
            float dy = __ldg(offb + (size_t)(i * 18 + 2 * k) * WW + px);
            float dx = __ldg(offb + (size_t)(i * 18 + 2 * k + 1) * WW + px);
            float ys  = (float)h + (float)((k / 3 - 1) * d) + dy;
            float xsf = (float)(w0 + px) + (float)((k % 3 - 1) * d) + dx;
            float y0f = floorf(ys), x0f = floorf(xsf);
            float wy1 = ys - y0f, wx1 = xsf - x0f, wy0 = 1.f - wy1, wx0 = 1.f - wx1;
            float y1f = y0f + 1.f, x1f = x0f + 1.f;
            float vy0 = (y0f >= 0.f && y0f <= 255.f) ? 1.f : 0.f;
            float vy1 = (y1f >= 0.f && y1f <= 255.f) ? 1.f : 0.f;
            float vx0 = (x0f >= 0.f && x0f <= 255.f) ? 1.f : 0.f;
            float vx1 = (x1f >= 0.f && x1f <= 255.f) ? 1.f : 0.f;
            u32 iy0 = (u32)(int)fminf(fmaxf(y0f, 0.f), 255.f);
            u32 iy1 = (u32)(int)fminf(fmaxf(y1f, 0.f), 255.f);
            u32 ix0 = (u32)(int)fminf(fmaxf(x0f, 0.f), 255.f);
            u32 ix1 = (u32)(int)fminf(fmaxf(x1f, 0.f), 255.f);
            uint4 o;
            o.x = ((iy0 * WW + ix0) * CC) * 4u;
            o.y = ((iy0 * WW + ix1) * CC) * 4u;
            o.z = ((iy1 * WW + ix0) * CC) * 4u;
            o.w = ((iy1 * WW + ix1) * CC) * 4u;
            float4 cw = make_float4(wy0 * wx0 * vy0 * vx0, wy0 * wx1 * vy0 * vx1,
                                    wy1 * wx0 * vy1 * vx0, wy1 * wx1 * vy1 * vx1);
            *(uint4*) &sG[(buf * TPX + px) * 8]     = o;
            *(float4*)&sG[(buf * TPX + px) * 8 + 4] = cw;
        }
    };

    setup(0, 0);
    __syncthreads();

    u32* sSu = (u32*)sS;

    for (int tap = 0; tap < ND * KK; tap++) {
        int p = tap & 1;

        // gather: group = 8 px, lane f loads 16B chunk f of each corner row
        {
            const float* gp = &sG[(p * TPX + grp * 8) * 8];
            uint4  o  = *(const uint4*) (gp);
            float4 cw = *(const float4*)(gp + 4);
            float4 c0 = __ldg((const float4*)(xTb + o.x) + f);
            float4 c1 = __ldg((const float4*)(xTb + o.y) + f);
            float4 c2 = __ldg((const float4*)(xTb + o.z) + f);
            float4 c3 = __ldg((const float4*)(xTb + o.w) + f);

            #pragma unroll
            for (int j = 0; j < 8; j++) {
                uint4 no; float4 ncw;
                float4 n0, n1, n2, n3;
                if (j < 7) {
                    const float* gq = &sG[(p * TPX + grp * 8 + j + 1) * 8];
                    no  = *(const uint4*) (gq);
                    ncw = *(const float4*)(gq + 4);
                    n0 = __ldg((const float4*)(xTb + no.x) + f);
                    n1 = __ldg((const float4*)(xTb + no.y) + f);
                    n2 = __ldg((const float4*)(xTb + no.z) + f);
                    n3 = __ldg((const float4*)(xTb + no.w) + f);
                }
                uint4 r;
                r.x = f2tf32(cw.x*c0.x + cw.y*c1.x + cw.z*c2.x + cw.w*c3.x);
                r.y = f2tf32(cw.x*c0.y + cw.y*c1.y + cw.z*c2.y + cw.w*c3.y);
                r.z = f2tf32(cw.x*c0.z + cw.y*c1.z + cw.z*c2.z + cw.w*c3.z);
                r.w = f2tf32(cw.x*c0.w + cw.y*c1.w + cw.z*c2.w + cw.w*c3.w);
                *(uint4*)&sSu[(grp * 8 + j) * SSTR + 4 * f] = r;
                if (j < 7) { o = no; cw = ncw; c0 = n0; c1 = n1; c2 = n2; c3 = n3; }
            }
        }

        if (tap + 1 < ND * KK) setup(tap + 1, 1 - p);

        __syncthreads();

        // einsum: A from smem, B direct from fragment-ordered global (L1-hit)
        {
            const float4* wF = (const float4*)g_weffF + (size_t)tap * 1024 + warp_n * 512;
            int arow = warp_m * 32 + lg;
            #pragma unroll
            for (int s2 = 0; s2 < 4; s2++) {
                int cofs = le * 16 + 4 * s2;
                uint4 a0lo = *(const uint4*)&sSu[(arow)      * SSTR + cofs];
                uint4 a0hi = *(const uint4*)&sSu[(arow + 8)  * SSTR + cofs];
                uint4 a1lo = *(const uint4*)&sSu[(arow + 16) * SSTR + cofs];
                uint4 a1hi = *(const uint4*)&sSu[(arow + 24) * SSTR + cofs];
                #pragma unroll
                for (int nt = 0; nt < 4; nt++) {
                    float4 bvf = __ldg(wF + (s2 * 4 + nt) * 32 + lane);
                    u32 b0 = __float_as_uint(bvf.x), b1 = __float_as_uint(bvf.y);
                    u32 b2 = __float_as_uint(bvf.z), b3 = __float_as_uint(bvf.w);
                    mma_tf32(acc[0][nt], a0lo.x, a0hi.x, a0lo.y, a0hi.y, b0, b1);
                    mma_tf32(acc[0][nt], a0lo.z, a0hi.z, a0lo.w, a0hi.w, b2, b3);
                    mma_tf32(acc[1][nt], a1lo.x, a1hi.x, a1lo.y, a1hi.y, b0, b1);
                    mma_tf32(acc[1][nt], a1lo.z, a1hi.z, a1lo.w, a1hi.w, b2, b3);
                }
            }
        }

        __syncthreads();
    }

    // epilogue: frags -> smem [oo][px] -> coalesced stores
    float* sOut = sm;
    #pragma unroll
    for (int mt = 0; mt < 2; mt++) {
        int px0 = warp_m * 32 + mt * 16 + lg;
        #pragma unroll
        for (int nt = 0; nt < 4; nt++) {
            int oo = warp_n * 32 + nt * 8 + 2 * le;
            sOut[oo * TPX + px0]           = acc[mt][nt][0];
            sOut[(oo + 1) * TPX + px0]     = acc[mt][nt][1];
            sOut[oo * TPX + px0 + 8]       = acc[mt][nt][2];
            sOut[(oo + 1) * TPX + px0 + 8] = acc[mt][nt][3];
        }
    }
    __syncthreads();
    {
        int row = tid >> 2;
        int f0  = tid & 3;
        float4* op = (float4*)(out + (((size_t)(b * CC + row) * HH + h) * WW + w0));
        const float4* sp = (const float4*)(sOut + row * TPX);
        #pragma unroll
        for (int j = 0; j < 8; j++) op[f0 + j * 4] = sp[f0 + j * 4];
    }
}

// ---------------- launch ------------------------------------------------------
extern "C" void kernel_launch(void* const* d_in, const int* in_sizes, int n_in,
                              void* d_out, int out_size) {
    const float* x     = (const float*)d_in[0];
    const float* Woff  = (const float*)d_in[1];
    const float* boff  = (const float*)d_in[2];
    const float* Wd    = (const float*)d_in[3];
    const float* Wfuse = (const float*)d_in[4];
    float* out = (float*)d_out;

    int smem_main = SMF_TOT * 4;
    int smem_off  = 2 * 130 * OSTR * 4;
    static int smem_set = 0;
    if (!smem_set) {
        cudaFuncSetAttribute(main_kernel,
                             cudaFuncAttributeMaxDynamicSharedMemorySize, smem_main);
        cudaFuncSetAttribute(offconv_kernel,
                             cudaFuncAttributeMaxDynamicSharedMemorySize, smem_off);
        smem_set = 1;
    }

    transpose_kernel<<<dim3(WW / 32, CC / 32, BB * HH), dim3(32, 8)>>>(x);
    weff_kernel<<<(ND * KK * CC * CC + 255) / 256, 256>>>(Wd, Wfuse);
    woff_kernel<<<(KK * CC * CC + 255) / 256, 256>>>(Woff);
    offconv_kernel<<<dim3(WW / TPX, BB * HH), 256, smem_off>>>(boff);
    main_kernel<<<dim3(WW / TPX, BB * HH), 256, smem_main>>>(out);
}